// round 9
// baseline (speedup 1.0000x reference)
#include <cuda_runtime.h>
#include <cuda_fp16.h>

#define NN 100000
#define EE 1600000
#define FIN 128
#define HID 64

// ---- scratch (static __device__ — no allocation) ----
__device__ __align__(16) __half2 g_h1h[NN * 32];  // h1, fp16, feature pairs
__device__ __align__(16) __half2 g_h2h[NN * 32];  // h2, fp16
__device__ __align__(16) float g_as1[NN * 4];
__device__ __align__(16) float g_ad1[NN * 4];
__device__ __align__(16) float g_agg1[NN * HID];
__device__ __align__(16) float g_as2[NN];
__device__ __align__(16) float g_ad2[NN];
__device__ int g_cnt[NN];    // degree by dst (zero at load; re-zeroed by agg2f each call)
__device__ int g_rs[NN];     // CSR row starts (unordered ranges)
__device__ int g_cur[NN];    // fill cursors
__device__ int g_srcs[EE];   // CSR: src per incident edge, grouped by dst
__device__ int g_total;      // range-allocation cursor (reset by k_fill each call)

__device__ __forceinline__ float lrelu(float t) { return fmaxf(t, 0.2f * t); }

// ---------------- layer-1 GEMM (+ fused degree histogram) ----------------
__global__ void k_gemm1h(const float* __restrict__ x, const float* __restrict__ W1,
                         const float* __restrict__ a_src, const float* __restrict__ a_dst,
                         const int* __restrict__ ei) {
    __shared__ float2 Wsh[FIN * 32];
    int tid = threadIdx.x;

    // fused histogram: exactly 2 edges per thread (3125*512 == EE)
    {
        int e = blockIdx.x * 512 + tid;
        atomicAdd(&g_cnt[__ldg(&ei[EE + e])], 1);
        atomicAdd(&g_cnt[__ldg(&ei[EE + e + 256])], 1);
    }

    for (int i = tid; i < FIN * 32; i += 256) Wsh[i] = ((const float2*)W1)[i];
    __syncthreads();

    int lane = tid & 31, w = tid >> 5;
    int r0 = (blockIdx.x * 8 + w) * 4;

    float xr[4][4];
#pragma unroll
    for (int i = 0; i < 4; i++)
#pragma unroll
        for (int j = 0; j < 4; j++)
            xr[i][j] = x[(r0 + i) * FIN + 32 * j + lane];

    float acc0[4] = {}, acc1[4] = {};
#pragma unroll
    for (int k = 0; k < FIN; k++) {
        float2 wv = Wsh[k * 32 + lane];
#pragma unroll
        for (int i = 0; i < 4; i++) {
            float xk = __shfl_sync(0xffffffffu, xr[i][k >> 5], k & 31);
            acc0[i] += xk * wv.x;
            acc1[i] += xk * wv.y;
        }
    }

    float s0 = __ldg(&a_src[2 * lane]), s1 = __ldg(&a_src[2 * lane + 1]);
    float d0 = __ldg(&a_dst[2 * lane]), d1 = __ldg(&a_dst[2 * lane + 1]);

#pragma unroll
    for (int i = 0; i < 4; i++) {
        int row = r0 + i;
        g_h1h[row * 32 + lane] = __floats2half2_rn(acc0[i], acc1[i]);
        float pa = acc0[i] * s0 + acc1[i] * s1;
        float pd = acc0[i] * d0 + acc1[i] * d1;
#pragma unroll
        for (int off = 4; off; off >>= 1) {
            pa += __shfl_xor_sync(0xffffffffu, pa, off);
            pd += __shfl_xor_sync(0xffffffffu, pd, off);
        }
        if ((lane & 7) == 0) {
            g_as1[row * 4 + (lane >> 3)] = pa;
            g_ad1[row * 4 + (lane >> 3)] = pd;
        }
    }
}

// ---------------- CSR range allocation ----------------
__global__ void k_alloc() {
    int i = blockIdx.x * blockDim.x + threadIdx.x;
    int lane = threadIdx.x & 31;
    int c = (i < NN) ? g_cnt[i] : 0;
    int s = c;
#pragma unroll
    for (int off = 1; off < 32; off <<= 1) {
        int t = __shfl_up_sync(0xffffffffu, s, off);
        if (lane >= off) s += t;
    }
    int wtot = __shfl_sync(0xffffffffu, s, 31);
    int base = 0;
    if (lane == 31) base = atomicAdd(&g_total, wtot);
    base = __shfl_sync(0xffffffffu, base, 31);
    if (i < NN) {
        int r = base + s - c;
        g_rs[i] = r;
        g_cur[i] = r;
    }
}

__global__ void k_fill(const int* __restrict__ ei) {
    int e = blockIdx.x * blockDim.x + threadIdx.x;
    if (e == 0) g_total = 0;
    if (e < EE) {
        int s = __ldg(&ei[e]);
        int d = __ldg(&ei[EE + e]);
        int p = atomicAdd(&g_cur[d], 1);
        g_srcs[p] = s;
    }
}

// ---------------- layer-1 gather aggregation: one warp per dst node ----------------
// Warp-role dedup: per 8-edge chunk, lane (e*4+h) computes exp for (edge e, head h);
// accumulation lanes fetch it via shfl. No redundant score loads or exp.
__global__ void k_agg1() {
    int n = blockIdx.x * 8 + (threadIdx.x >> 5);
    if (n >= NN) return;
    int lane = threadIdx.x & 31;
    int head = lane >> 3;          // accumulation head (8 lanes per head)

    int rs = g_rs[n];
    int deg = g_cnt[n];
    int m = deg < 32 ? deg : 32;
    int idx = (lane < m) ? g_srcs[rs + lane] : 0;
    float adv_e = g_ad1[n * 4 + (lane & 3)];   // exp-role head = lane&3

    float ax = 0.f, ay = 0.f, den = 0.f;

    for (int j0 = 0; j0 < m; j0 += 8) {
        int eL = j0 + (lane >> 2);             // edge this lane computes exp for
        int se = __shfl_sync(0xffffffffu, idx, eL & 31);
        float sc = g_as1[se * 4 + (lane & 3)];
        float ee = (eL < m) ? __expf(lrelu(sc + adv_e)) : 0.f;
#pragma unroll
        for (int k = 0; k < 8; k++) {
            if (j0 + k < m) {                  // warp-uniform guard
                float ek = __shfl_sync(0xffffffffu, ee, (k << 2) | head);
                int sk = __shfl_sync(0xffffffffu, idx, j0 + k);
                float2 v = __half22float2(g_h1h[sk * 32 + lane]);
                den += ek;
                ax += ek * v.x;
                ay += ek * v.y;
            }
        }
    }
    for (int j = 32; j < deg; j++) {           // rare tail (Poisson(16))
        int s0 = g_srcs[rs + j];
        float e0 = __expf(lrelu(g_as1[s0 * 4 + head] + g_ad1[n * 4 + head]));
        float2 v0 = __half22float2(g_h1h[s0 * 32 + lane]);
        den += e0;
        ax += e0 * v0.x;
        ay += e0 * v0.y;
    }
    float inv = 1.f / (den + 1e-16f);
    float2 o;
    o.x = ax * inv;
    o.y = ay * inv;
    ((float2*)g_agg1)[n * 32 + lane] = o;
}

// ---------------- layer-2 GEMM: h2 = relu(agg1 + b1) @ W2 (fp16 out) + dots (1 head) ----------------
__global__ void k_gemm2(const float* __restrict__ W2, const float* __restrict__ b1,
                        const float* __restrict__ a_src, const float* __restrict__ a_dst) {
    __shared__ float2 Wsh[HID * 32];
    int tid = threadIdx.x;
    for (int i = tid; i < HID * 32; i += 256) Wsh[i] = ((const float2*)W2)[i];
    __syncthreads();

    int lane = tid & 31, w = tid >> 5;
    int r0 = (blockIdx.x * 8 + w) * 4;
    float b0 = __ldg(&b1[2 * lane]), b1v = __ldg(&b1[2 * lane + 1]);

    float2 xr[4];
#pragma unroll
    for (int i = 0; i < 4; i++) {
        float2 v = ((const float2*)g_agg1)[(r0 + i) * 32 + lane];
        xr[i].x = fmaxf(v.x + b0, 0.f);
        xr[i].y = fmaxf(v.y + b1v, 0.f);
    }

    float acc0[4] = {}, acc1[4] = {};
#pragma unroll
    for (int k = 0; k < HID; k++) {
        float2 wv = Wsh[k * 32 + lane];
#pragma unroll
        for (int i = 0; i < 4; i++) {
            float xk = __shfl_sync(0xffffffffu, (k & 1) ? xr[i].y : xr[i].x, k >> 1);
            acc0[i] += xk * wv.x;
            acc1[i] += xk * wv.y;
        }
    }

    float s0 = __ldg(&a_src[2 * lane]), s1 = __ldg(&a_src[2 * lane + 1]);
    float d0 = __ldg(&a_dst[2 * lane]), d1 = __ldg(&a_dst[2 * lane + 1]);

#pragma unroll
    for (int i = 0; i < 4; i++) {
        int row = r0 + i;
        g_h2h[row * 32 + lane] = __floats2half2_rn(acc0[i], acc1[i]);
        float pa = acc0[i] * s0 + acc1[i] * s1;
        float pd = acc0[i] * d0 + acc1[i] * d1;
#pragma unroll
        for (int off = 16; off; off >>= 1) {
            pa += __shfl_xor_sync(0xffffffffu, pa, off);
            pd += __shfl_xor_sync(0xffffffffu, pd, off);
        }
        if (lane == 0) {
            g_as2[row] = pa;
            g_ad2[row] = pd;
        }
    }
}

// ---------------- layer-2 gather aggregation fused with final projection ----------------
// 1 head: each lane computes the exp of its own prefetched edge; den via butterfly.
__global__ void k_agg2f(const float* __restrict__ b2, const float* __restrict__ Wc,
                        const float* __restrict__ bc, float* __restrict__ out) {
    int n = blockIdx.x * 8 + (threadIdx.x >> 5);
    if (n >= NN) return;
    int lane = threadIdx.x & 31;

    int rs = g_rs[n];
    int deg = g_cnt[n];
    float adv = g_ad2[n];
    int m = deg < 32 ? deg : 32;
    int idx = (lane < m) ? g_srcs[rs + lane] : 0;

    float sc = g_as2[idx];
    float ee = (lane < m) ? __expf(lrelu(sc + adv)) : 0.f;
    float den = ee;
#pragma unroll
    for (int off = 16; off; off >>= 1) den += __shfl_xor_sync(0xffffffffu, den, off);

    float ax = 0.f, ay = 0.f;
    int j = 0;
    for (; j + 4 <= m; j += 4) {
#pragma unroll
        for (int k = 0; k < 4; k++) {
            float ek = __shfl_sync(0xffffffffu, ee, j + k);
            int sk = __shfl_sync(0xffffffffu, idx, j + k);
            float2 v = __half22float2(g_h2h[sk * 32 + lane]);
            ax += ek * v.x;
            ay += ek * v.y;
        }
    }
    for (; j < m; j++) {
        float ek = __shfl_sync(0xffffffffu, ee, j);
        int sk = __shfl_sync(0xffffffffu, idx, j);
        float2 v = __half22float2(g_h2h[sk * 32 + lane]);
        ax += ek * v.x;
        ay += ek * v.y;
    }
    for (j = 32; j < deg; j++) {              // rare tail
        int s0 = g_srcs[rs + j];
        float e0 = __expf(lrelu(g_as2[s0] + adv));
        float2 v0 = __half22float2(g_h2h[s0 * 32 + lane]);
        den += e0;
        ax += e0 * v0.x;
        ay += e0 * v0.y;
    }
    float inv = 1.f / (den + 1e-16f);
    float v = fmaxf(ax * inv + __ldg(&b2[2 * lane]), 0.f) * __ldg(&Wc[2 * lane])
            + fmaxf(ay * inv + __ldg(&b2[2 * lane + 1]), 0.f) * __ldg(&Wc[2 * lane + 1]);
#pragma unroll
    for (int off = 16; off; off >>= 1) v += __shfl_xor_sync(0xffffffffu, v, off);
    if (lane == 0) {
        out[n] = v + __ldg(&bc[0]);
        g_cnt[n] = 0;  // restore invariant for next call's histogram
    }
}

extern "C" void kernel_launch(void* const* d_in, const int* in_sizes, int n_in,
                              void* d_out, int out_size) {
    const float* x      = (const float*)d_in[0];
    const int* ei       = (const int*)d_in[1];   // JAX x64 disabled -> int32
    const float* W1     = (const float*)d_in[2];
    const float* a_src1 = (const float*)d_in[3];
    const float* a_dst1 = (const float*)d_in[4];
    const float* b1     = (const float*)d_in[5];
    const float* W2     = (const float*)d_in[6];
    const float* a_src2 = (const float*)d_in[7];
    const float* a_dst2 = (const float*)d_in[8];
    const float* b2     = (const float*)d_in[9];
    const float* Wc     = (const float*)d_in[10];
    const float* bc     = (const float*)d_in[11];
    float* out          = (float*)d_out;
    (void)in_sizes; (void)n_in; (void)out_size;

    k_gemm1h<<<3125, 256>>>(x, W1, a_src1, a_dst1, ei);  // 1: GEMM1 + degree hist
    k_alloc<<<(NN + 255) / 256, 256>>>();                // 2: CSR range alloc
    k_fill<<<(EE + 255) / 256, 256>>>(ei);               // 3: CSR fill
    k_agg1<<<12500, 256>>>();                            // 4: <- ncu sample
    k_gemm2<<<3125, 256>>>(W2, b1, a_src2, a_dst2);      // 5
    k_agg2f<<<12500, 256>>>(b2, Wc, bc, out);            // 6
}

// round 10
// speedup vs baseline: 1.1328x; 1.1328x over previous
#include <cuda_runtime.h>
#include <cuda_fp16.h>

#define NN 100000
#define EE 1600000
#define FIN 128
#define HID 64

// ---- scratch (static __device__ — no allocation) ----
__device__ __align__(16) __half2 g_h1h[NN * 32];  // h1, fp16, feature pairs
__device__ __align__(16) __half2 g_h2h[NN * 32];  // h2, fp16
__device__ __align__(16) float g_as1[NN * 4];
__device__ __align__(16) float g_ad1[NN * 4];
__device__ __align__(16) float g_agg1[NN * HID];
__device__ __align__(16) float g_as2[NN];
__device__ __align__(16) float g_ad2[NN];
__device__ int g_cnt[NN];    // degree by dst (zero at load; re-zeroed by agg2f each call)
__device__ int g_rs[NN];     // CSR row starts (unordered ranges)
__device__ int g_cur[NN];    // fill cursors
__device__ int g_srcs[EE];   // CSR: src per incident edge, grouped by dst
__device__ int g_total;      // range-allocation cursor (reset by k_fill each call)

__device__ __forceinline__ float lrelu(float t) { return fmaxf(t, 0.2f * t); }

// ---------------- layer-1 GEMM (+ fused degree histogram) ----------------
// Per warp: 4 rows. x rows stored TRANSPOSED in smem (one LDS.128 broadcast/k
// replaces 4 SHFLs -> 2 MIO ops per k instead of 5).
__global__ void k_gemm1h(const float* __restrict__ x, const float* __restrict__ W1,
                         const float* __restrict__ a_src, const float* __restrict__ a_dst,
                         const int* __restrict__ ei) {
    __shared__ float2 Wsh[FIN * 32];      // 32 KB
    __shared__ float4 Xsh[8][FIN];        // 16 KB: [warp][k] = x rows r0..r0+3 at k
    int tid = threadIdx.x;

    // fused histogram: exactly 2 edges per thread (3125*512 == EE)
    {
        int e = blockIdx.x * 512 + tid;
        atomicAdd(&g_cnt[__ldg(&ei[EE + e])], 1);
        atomicAdd(&g_cnt[__ldg(&ei[EE + e + 256])], 1);
    }

    for (int i = tid; i < FIN * 32; i += 256) Wsh[i] = ((const float2*)W1)[i];

    int lane = tid & 31, w = tid >> 5;
    int r0 = (blockIdx.x * 8 + w) * 4;

    // load 4 rows coalesced, store transposed (lane holds k=32j+lane for all 4 rows)
#pragma unroll
    for (int j = 0; j < 4; j++) {
        float4 v;
        v.x = x[(r0 + 0) * FIN + 32 * j + lane];
        v.y = x[(r0 + 1) * FIN + 32 * j + lane];
        v.z = x[(r0 + 2) * FIN + 32 * j + lane];
        v.w = x[(r0 + 3) * FIN + 32 * j + lane];
        Xsh[w][32 * j + lane] = v;
    }
    __syncthreads();

    float acc0[4] = {}, acc1[4] = {};
#pragma unroll
    for (int k = 0; k < FIN; k++) {
        float4 xv = Xsh[w][k];            // LDS.128 broadcast
        float2 wv = Wsh[k * 32 + lane];   // LDS.64
        acc0[0] += xv.x * wv.x;  acc1[0] += xv.x * wv.y;
        acc0[1] += xv.y * wv.x;  acc1[1] += xv.y * wv.y;
        acc0[2] += xv.z * wv.x;  acc1[2] += xv.z * wv.y;
        acc0[3] += xv.w * wv.x;  acc1[3] += xv.w * wv.y;
    }

    float s0 = __ldg(&a_src[2 * lane]), s1 = __ldg(&a_src[2 * lane + 1]);
    float d0 = __ldg(&a_dst[2 * lane]), d1 = __ldg(&a_dst[2 * lane + 1]);

#pragma unroll
    for (int i = 0; i < 4; i++) {
        int row = r0 + i;
        g_h1h[row * 32 + lane] = __floats2half2_rn(acc0[i], acc1[i]);
        float pa = acc0[i] * s0 + acc1[i] * s1;
        float pd = acc0[i] * d0 + acc1[i] * d1;
#pragma unroll
        for (int off = 4; off; off >>= 1) {
            pa += __shfl_xor_sync(0xffffffffu, pa, off);
            pd += __shfl_xor_sync(0xffffffffu, pd, off);
        }
        if ((lane & 7) == 0) {
            g_as1[row * 4 + (lane >> 3)] = pa;
            g_ad1[row * 4 + (lane >> 3)] = pd;
        }
    }
}

// ---------------- CSR range allocation ----------------
__global__ void k_alloc() {
    int i = blockIdx.x * blockDim.x + threadIdx.x;
    int lane = threadIdx.x & 31;
    int c = (i < NN) ? g_cnt[i] : 0;
    int s = c;
#pragma unroll
    for (int off = 1; off < 32; off <<= 1) {
        int t = __shfl_up_sync(0xffffffffu, s, off);
        if (lane >= off) s += t;
    }
    int wtot = __shfl_sync(0xffffffffu, s, 31);
    int base = 0;
    if (lane == 31) base = atomicAdd(&g_total, wtot);
    base = __shfl_sync(0xffffffffu, base, 31);
    if (i < NN) {
        int r = base + s - c;
        g_rs[i] = r;
        g_cur[i] = r;
    }
}

__global__ void k_fill(const int* __restrict__ ei) {
    int e = blockIdx.x * blockDim.x + threadIdx.x;
    if (e == 0) g_total = 0;
    if (e < EE) {
        int s = __ldg(&ei[e]);
        int d = __ldg(&ei[EE + e]);
        int p = atomicAdd(&g_cur[d], 1);
        g_srcs[p] = s;
    }
}

// ---------------- layer-1 gather aggregation: one warp per dst node (round-8 form) ----------------
__global__ void k_agg1() {
    int n = blockIdx.x * 8 + (threadIdx.x >> 5);
    if (n >= NN) return;
    int lane = threadIdx.x & 31;
    int head = lane >> 3;

    int rs = g_rs[n];
    int deg = g_cnt[n];
    float adv = g_ad1[n * 4 + head];

    float ax = 0.f, ay = 0.f, den = 0.f;

    int j = 0;
    for (; j + 4 <= deg; j += 4) {
        int s0 = g_srcs[rs + j],     s1 = g_srcs[rs + j + 1];
        int s2 = g_srcs[rs + j + 2], s3 = g_srcs[rs + j + 3];
        float t0 = g_as1[s0 * 4 + head] + adv;
        float t1 = g_as1[s1 * 4 + head] + adv;
        float t2 = g_as1[s2 * 4 + head] + adv;
        float t3 = g_as1[s3 * 4 + head] + adv;
        float2 v0 = __half22float2(g_h1h[s0 * 32 + lane]);
        float2 v1 = __half22float2(g_h1h[s1 * 32 + lane]);
        float2 v2 = __half22float2(g_h1h[s2 * 32 + lane]);
        float2 v3 = __half22float2(g_h1h[s3 * 32 + lane]);
        float e0 = __expf(lrelu(t0)), e1 = __expf(lrelu(t1));
        float e2 = __expf(lrelu(t2)), e3 = __expf(lrelu(t3));
        den += (e0 + e1) + (e2 + e3);
        ax += e0 * v0.x + e1 * v1.x + e2 * v2.x + e3 * v3.x;
        ay += e0 * v0.y + e1 * v1.y + e2 * v2.y + e3 * v3.y;
    }
    for (; j < deg; j++) {
        int s0 = g_srcs[rs + j];
        float t0 = g_as1[s0 * 4 + head] + adv;
        float2 v0 = __half22float2(g_h1h[s0 * 32 + lane]);
        float e0 = __expf(lrelu(t0));
        den += e0;
        ax += e0 * v0.x;
        ay += e0 * v0.y;
    }
    float inv = 1.f / (den + 1e-16f);
    float2 o;
    o.x = ax * inv;
    o.y = ay * inv;
    ((float2*)g_agg1)[n * 32 + lane] = o;
}

// ---------------- layer-2 GEMM: h2 = relu(agg1 + b1) @ W2 (fp16 out) + dots (1 head) ----------------
__global__ void k_gemm2(const float* __restrict__ W2, const float* __restrict__ b1,
                        const float* __restrict__ a_src, const float* __restrict__ a_dst) {
    __shared__ float2 Wsh[HID * 32];      // 16 KB
    __shared__ float4 Xsh[8][HID];        // 8 KB
    int tid = threadIdx.x;
    for (int i = tid; i < HID * 32; i += 256) Wsh[i] = ((const float2*)W2)[i];

    int lane = tid & 31, w = tid >> 5;
    int r0 = (blockIdx.x * 8 + w) * 4;
    float b0 = __ldg(&b1[2 * lane]), b1v = __ldg(&b1[2 * lane + 1]);

    // lane owns cols (2lane, 2lane+1) of 4 rows -> two transposed STS.128
    {
        float4 c0, c1;  // column 2lane / 2lane+1, rows r0..r0+3
        float2 v0 = ((const float2*)g_agg1)[(r0 + 0) * 32 + lane];
        float2 v1 = ((const float2*)g_agg1)[(r0 + 1) * 32 + lane];
        float2 v2 = ((const float2*)g_agg1)[(r0 + 2) * 32 + lane];
        float2 v3 = ((const float2*)g_agg1)[(r0 + 3) * 32 + lane];
        c0.x = fmaxf(v0.x + b0, 0.f);  c1.x = fmaxf(v0.y + b1v, 0.f);
        c0.y = fmaxf(v1.x + b0, 0.f);  c1.y = fmaxf(v1.y + b1v, 0.f);
        c0.z = fmaxf(v2.x + b0, 0.f);  c1.z = fmaxf(v2.y + b1v, 0.f);
        c0.w = fmaxf(v3.x + b0, 0.f);  c1.w = fmaxf(v3.y + b1v, 0.f);
        Xsh[w][2 * lane] = c0;
        Xsh[w][2 * lane + 1] = c1;
    }
    __syncthreads();

    float acc0[4] = {}, acc1[4] = {};
#pragma unroll
    for (int k = 0; k < HID; k++) {
        float4 xv = Xsh[w][k];
        float2 wv = Wsh[k * 32 + lane];
        acc0[0] += xv.x * wv.x;  acc1[0] += xv.x * wv.y;
        acc0[1] += xv.y * wv.x;  acc1[1] += xv.y * wv.y;
        acc0[2] += xv.z * wv.x;  acc1[2] += xv.z * wv.y;
        acc0[3] += xv.w * wv.x;  acc1[3] += xv.w * wv.y;
    }

    float s0 = __ldg(&a_src[2 * lane]), s1 = __ldg(&a_src[2 * lane + 1]);
    float d0 = __ldg(&a_dst[2 * lane]), d1 = __ldg(&a_dst[2 * lane + 1]);

#pragma unroll
    for (int i = 0; i < 4; i++) {
        int row = r0 + i;
        g_h2h[row * 32 + lane] = __floats2half2_rn(acc0[i], acc1[i]);
        float pa = acc0[i] * s0 + acc1[i] * s1;
        float pd = acc0[i] * d0 + acc1[i] * d1;
#pragma unroll
        for (int off = 16; off; off >>= 1) {
            pa += __shfl_xor_sync(0xffffffffu, pa, off);
            pd += __shfl_xor_sync(0xffffffffu, pd, off);
        }
        if (lane == 0) {
            g_as2[row] = pa;
            g_ad2[row] = pd;
        }
    }
}

// ---------------- layer-2 gather aggregation fused with final projection (round-8 form) ----------------
__global__ void k_agg2f(const float* __restrict__ b2, const float* __restrict__ Wc,
                        const float* __restrict__ bc, float* __restrict__ out) {
    int n = blockIdx.x * 8 + (threadIdx.x >> 5);
    if (n >= NN) return;
    int lane = threadIdx.x & 31;

    int rs = g_rs[n];
    int deg = g_cnt[n];
    float adv = g_ad2[n];

    float ax = 0.f, ay = 0.f, den = 0.f;

    int j = 0;
    for (; j + 4 <= deg; j += 4) {
        int s0 = g_srcs[rs + j],     s1 = g_srcs[rs + j + 1];
        int s2 = g_srcs[rs + j + 2], s3 = g_srcs[rs + j + 3];
        float t0 = g_as2[s0] + adv, t1 = g_as2[s1] + adv;
        float t2 = g_as2[s2] + adv, t3 = g_as2[s3] + adv;
        float2 v0 = __half22float2(g_h2h[s0 * 32 + lane]);
        float2 v1 = __half22float2(g_h2h[s1 * 32 + lane]);
        float2 v2 = __half22float2(g_h2h[s2 * 32 + lane]);
        float2 v3 = __half22float2(g_h2h[s3 * 32 + lane]);
        float e0 = __expf(lrelu(t0)), e1 = __expf(lrelu(t1));
        float e2 = __expf(lrelu(t2)), e3 = __expf(lrelu(t3));
        den += (e0 + e1) + (e2 + e3);
        ax += e0 * v0.x + e1 * v1.x + e2 * v2.x + e3 * v3.x;
        ay += e0 * v0.y + e1 * v1.y + e2 * v2.y + e3 * v3.y;
    }
    for (; j < deg; j++) {
        int s0 = g_srcs[rs + j];
        float t0 = g_as2[s0] + adv;
        float2 v0 = __half22float2(g_h2h[s0 * 32 + lane]);
        float e0 = __expf(lrelu(t0));
        den += e0;
        ax += e0 * v0.x;
        ay += e0 * v0.y;
    }
    float inv = 1.f / (den + 1e-16f);
    float v = fmaxf(ax * inv + __ldg(&b2[2 * lane]), 0.f) * __ldg(&Wc[2 * lane])
            + fmaxf(ay * inv + __ldg(&b2[2 * lane + 1]), 0.f) * __ldg(&Wc[2 * lane + 1]);
#pragma unroll
    for (int off = 16; off; off >>= 1) v += __shfl_xor_sync(0xffffffffu, v, off);
    if (lane == 0) {
        out[n] = v + __ldg(&bc[0]);
        g_cnt[n] = 0;  // restore invariant for next call's histogram
    }
}

extern "C" void kernel_launch(void* const* d_in, const int* in_sizes, int n_in,
                              void* d_out, int out_size) {
    const float* x      = (const float*)d_in[0];
    const int* ei       = (const int*)d_in[1];   // JAX x64 disabled -> int32
    const float* W1     = (const float*)d_in[2];
    const float* a_src1 = (const float*)d_in[3];
    const float* a_dst1 = (const float*)d_in[4];
    const float* b1     = (const float*)d_in[5];
    const float* W2     = (const float*)d_in[6];
    const float* a_src2 = (const float*)d_in[7];
    const float* a_dst2 = (const float*)d_in[8];
    const float* b2     = (const float*)d_in[9];
    const float* Wc     = (const float*)d_in[10];
    const float* bc     = (const float*)d_in[11];
    float* out          = (float*)d_out;
    (void)in_sizes; (void)n_in; (void)out_size;

    k_gemm1h<<<3125, 256>>>(x, W1, a_src1, a_dst1, ei);  // 1: GEMM1 + degree hist
    k_alloc<<<(NN + 255) / 256, 256>>>();                // 2: CSR range alloc
    k_fill<<<(EE + 255) / 256, 256>>>(ei);               // 3: CSR fill
    k_agg1<<<12500, 256>>>();                            // 4: <- ncu sample
    k_gemm2<<<3125, 256>>>(W2, b1, a_src2, a_dst2);      // 5
    k_agg2f<<<12500, 256>>>(b2, Wc, bc, out);            // 6
}

// round 11
// speedup vs baseline: 1.2105x; 1.0685x over previous
#include <cuda_runtime.h>
#include <cuda_fp16.h>

#define NN 100000
#define EE 1600000
#define FIN 128
#define HID 64

// ---- scratch (static __device__ — no allocation) ----
__device__ __align__(16) __half2 g_h1h[NN * 32];  // h1, fp16, feature pairs (128B/row)
__device__ __align__(16) __half2 g_h2h[NN * 32];  // h2, fp16
__device__ __align__(16) float g_as1[NN * 4];
__device__ __align__(16) float g_ad1[NN * 4];
__device__ __align__(16) float g_agg1[NN * HID];
__device__ __align__(16) float g_as2[NN];
__device__ __align__(16) float g_ad2[NN];
__device__ int g_cnt[NN];    // degree by dst (zero at load; re-zeroed by agg2f each call)
__device__ int g_rs[NN];     // CSR row starts (unordered ranges)
__device__ int g_cur[NN];    // fill cursors
__device__ int g_srcs[EE];   // CSR: src per incident edge, grouped by dst
__device__ int g_total;      // range-allocation cursor (reset by k_fill each call)

__device__ __forceinline__ float lrelu(float t) { return fmaxf(t, 0.2f * t); }

// ---------------- layer-1 GEMM (+ fused degree histogram) ----------------
__global__ void k_gemm1h(const float* __restrict__ x, const float* __restrict__ W1,
                         const float* __restrict__ a_src, const float* __restrict__ a_dst,
                         const int* __restrict__ ei) {
    __shared__ float2 Wsh[FIN * 32];      // 32 KB
    __shared__ float4 Xsh[8][FIN];        // 16 KB: [warp][k] = x rows r0..r0+3 at k
    int tid = threadIdx.x;

    // fused histogram: exactly 2 edges per thread (3125*512 == EE)
    {
        int e = blockIdx.x * 512 + tid;
        atomicAdd(&g_cnt[__ldg(&ei[EE + e])], 1);
        atomicAdd(&g_cnt[__ldg(&ei[EE + e + 256])], 1);
    }

    for (int i = tid; i < FIN * 32; i += 256) Wsh[i] = ((const float2*)W1)[i];

    int lane = tid & 31, w = tid >> 5;
    int r0 = (blockIdx.x * 8 + w) * 4;

#pragma unroll
    for (int j = 0; j < 4; j++) {
        float4 v;
        v.x = x[(r0 + 0) * FIN + 32 * j + lane];
        v.y = x[(r0 + 1) * FIN + 32 * j + lane];
        v.z = x[(r0 + 2) * FIN + 32 * j + lane];
        v.w = x[(r0 + 3) * FIN + 32 * j + lane];
        Xsh[w][32 * j + lane] = v;
    }
    __syncthreads();

    float acc0[4] = {}, acc1[4] = {};
#pragma unroll
    for (int k = 0; k < FIN; k++) {
        float4 xv = Xsh[w][k];            // LDS.128 broadcast
        float2 wv = Wsh[k * 32 + lane];   // LDS.64
        acc0[0] += xv.x * wv.x;  acc1[0] += xv.x * wv.y;
        acc0[1] += xv.y * wv.x;  acc1[1] += xv.y * wv.y;
        acc0[2] += xv.z * wv.x;  acc1[2] += xv.z * wv.y;
        acc0[3] += xv.w * wv.x;  acc1[3] += xv.w * wv.y;
    }

    float s0 = __ldg(&a_src[2 * lane]), s1 = __ldg(&a_src[2 * lane + 1]);
    float d0 = __ldg(&a_dst[2 * lane]), d1 = __ldg(&a_dst[2 * lane + 1]);

#pragma unroll
    for (int i = 0; i < 4; i++) {
        int row = r0 + i;
        g_h1h[row * 32 + lane] = __floats2half2_rn(acc0[i], acc1[i]);
        float pa = acc0[i] * s0 + acc1[i] * s1;
        float pd = acc0[i] * d0 + acc1[i] * d1;
#pragma unroll
        for (int off = 4; off; off >>= 1) {
            pa += __shfl_xor_sync(0xffffffffu, pa, off);
            pd += __shfl_xor_sync(0xffffffffu, pd, off);
        }
        if ((lane & 7) == 0) {
            g_as1[row * 4 + (lane >> 3)] = pa;
            g_ad1[row * 4 + (lane >> 3)] = pd;
        }
    }
}

// ---------------- CSR range allocation ----------------
__global__ void k_alloc() {
    int i = blockIdx.x * blockDim.x + threadIdx.x;
    int lane = threadIdx.x & 31;
    int c = (i < NN) ? g_cnt[i] : 0;
    int s = c;
#pragma unroll
    for (int off = 1; off < 32; off <<= 1) {
        int t = __shfl_up_sync(0xffffffffu, s, off);
        if (lane >= off) s += t;
    }
    int wtot = __shfl_sync(0xffffffffu, s, 31);
    int base = 0;
    if (lane == 31) base = atomicAdd(&g_total, wtot);
    base = __shfl_sync(0xffffffffu, base, 31);
    if (i < NN) {
        int r = base + s - c;
        g_rs[i] = r;
        g_cur[i] = r;
    }
}

__global__ void k_fill(const int* __restrict__ ei) {
    int e = blockIdx.x * blockDim.x + threadIdx.x;
    if (e == 0) g_total = 0;
    if (e < EE) {
        int s = __ldg(&ei[e]);
        int d = __ldg(&ei[EE + e]);
        int p = atomicAdd(&g_cur[d], 1);
        g_srcs[p] = s;
    }
}

// ---------------- layer-1 gather aggregation ----------------
// Warp = 4 groups of 8 lanes; each group owns an edge, each lane owns features
// 8q..8q+7 (one LDG.128). Per-head den partitions across groups; recombined by
// shfl_xor(8,16) in the epilogue. No intra-loop shfl.
__global__ void k_agg1() {
    int n = blockIdx.x * 8 + (threadIdx.x >> 5);
    if (n >= NN) return;
    int lane = threadIdx.x & 31;
    int grp = lane >> 3;           // edge slot 0..3
    int q = lane & 7;              // feature octet: features 8q..8q+7
    int head = q >> 1;

    int rs = g_rs[n];
    int deg = g_cnt[n];
    float adv = g_ad1[n * 4 + head];

    float a0 = 0.f, a1 = 0.f, a2 = 0.f, a3 = 0.f;
    float a4 = 0.f, a5 = 0.f, a6 = 0.f, a7 = 0.f, den = 0.f;

    const float4* h4 = (const float4*)g_h1h;   // 8 float4 per node row
    for (int j = 0; j < deg; j += 8) {
        int j0 = j + grp, j1 = j + grp + 4;
        int s0 = g_srcs[rs + (j0 < deg ? j0 : deg - 1)];
        int s1 = g_srcs[rs + (j1 < deg ? j1 : deg - 1)];
        float c0 = g_as1[s0 * 4 + head];
        float c1 = g_as1[s1 * 4 + head];
        float4 r0 = h4[s0 * 8 + q];
        float4 r1 = h4[s1 * 8 + q];
        float e0 = (j0 < deg) ? __expf(lrelu(c0 + adv)) : 0.f;
        float e1 = (j1 < deg) ? __expf(lrelu(c1 + adv)) : 0.f;
        den += e0 + e1;
        const __half2* p0 = (const __half2*)&r0;
        const __half2* p1 = (const __half2*)&r1;
        float2 v;
        v = __half22float2(p0[0]); a0 += e0 * v.x; a1 += e0 * v.y;
        v = __half22float2(p0[1]); a2 += e0 * v.x; a3 += e0 * v.y;
        v = __half22float2(p0[2]); a4 += e0 * v.x; a5 += e0 * v.y;
        v = __half22float2(p0[3]); a6 += e0 * v.x; a7 += e0 * v.y;
        v = __half22float2(p1[0]); a0 += e1 * v.x; a1 += e1 * v.y;
        v = __half22float2(p1[1]); a2 += e1 * v.x; a3 += e1 * v.y;
        v = __half22float2(p1[2]); a4 += e1 * v.x; a5 += e1 * v.y;
        v = __half22float2(p1[3]); a6 += e1 * v.x; a7 += e1 * v.y;
    }
#pragma unroll
    for (int off = 8; off <= 16; off <<= 1) {
        den += __shfl_xor_sync(0xffffffffu, den, off);
        a0 += __shfl_xor_sync(0xffffffffu, a0, off);
        a1 += __shfl_xor_sync(0xffffffffu, a1, off);
        a2 += __shfl_xor_sync(0xffffffffu, a2, off);
        a3 += __shfl_xor_sync(0xffffffffu, a3, off);
        a4 += __shfl_xor_sync(0xffffffffu, a4, off);
        a5 += __shfl_xor_sync(0xffffffffu, a5, off);
        a6 += __shfl_xor_sync(0xffffffffu, a6, off);
        a7 += __shfl_xor_sync(0xffffffffu, a7, off);
    }
    float inv = 1.f / (den + 1e-16f);
    if (grp == 0) {
        float4* dst = (float4*)g_agg1 + n * 16 + q * 2;
        float4 o;
        o.x = a0 * inv; o.y = a1 * inv; o.z = a2 * inv; o.w = a3 * inv;
        dst[0] = o;
        o.x = a4 * inv; o.y = a5 * inv; o.z = a6 * inv; o.w = a7 * inv;
        dst[1] = o;
    }
}

// ---------------- layer-2 GEMM: h2 = relu(agg1 + b1) @ W2 (fp16 out) + dots (1 head) ----------------
__global__ void k_gemm2(const float* __restrict__ W2, const float* __restrict__ b1,
                        const float* __restrict__ a_src, const float* __restrict__ a_dst) {
    __shared__ float2 Wsh[HID * 32];      // 16 KB
    __shared__ float4 Xsh[8][HID];        // 8 KB
    int tid = threadIdx.x;
    for (int i = tid; i < HID * 32; i += 256) Wsh[i] = ((const float2*)W2)[i];

    int lane = tid & 31, w = tid >> 5;
    int r0 = (blockIdx.x * 8 + w) * 4;
    float b0 = __ldg(&b1[2 * lane]), b1v = __ldg(&b1[2 * lane + 1]);

    {
        float4 c0, c1;
        float2 v0 = ((const float2*)g_agg1)[(r0 + 0) * 32 + lane];
        float2 v1 = ((const float2*)g_agg1)[(r0 + 1) * 32 + lane];
        float2 v2 = ((const float2*)g_agg1)[(r0 + 2) * 32 + lane];
        float2 v3 = ((const float2*)g_agg1)[(r0 + 3) * 32 + lane];
        c0.x = fmaxf(v0.x + b0, 0.f);  c1.x = fmaxf(v0.y + b1v, 0.f);
        c0.y = fmaxf(v1.x + b0, 0.f);  c1.y = fmaxf(v1.y + b1v, 0.f);
        c0.z = fmaxf(v2.x + b0, 0.f);  c1.z = fmaxf(v2.y + b1v, 0.f);
        c0.w = fmaxf(v3.x + b0, 0.f);  c1.w = fmaxf(v3.y + b1v, 0.f);
        Xsh[w][2 * lane] = c0;
        Xsh[w][2 * lane + 1] = c1;
    }
    __syncthreads();

    float acc0[4] = {}, acc1[4] = {};
#pragma unroll
    for (int k = 0; k < HID; k++) {
        float4 xv = Xsh[w][k];
        float2 wv = Wsh[k * 32 + lane];
        acc0[0] += xv.x * wv.x;  acc1[0] += xv.x * wv.y;
        acc0[1] += xv.y * wv.x;  acc1[1] += xv.y * wv.y;
        acc0[2] += xv.z * wv.x;  acc1[2] += xv.z * wv.y;
        acc0[3] += xv.w * wv.x;  acc1[3] += xv.w * wv.y;
    }

    float s0 = __ldg(&a_src[2 * lane]), s1 = __ldg(&a_src[2 * lane + 1]);
    float d0 = __ldg(&a_dst[2 * lane]), d1 = __ldg(&a_dst[2 * lane + 1]);

#pragma unroll
    for (int i = 0; i < 4; i++) {
        int row = r0 + i;
        g_h2h[row * 32 + lane] = __floats2half2_rn(acc0[i], acc1[i]);
        float pa = acc0[i] * s0 + acc1[i] * s1;
        float pd = acc0[i] * d0 + acc1[i] * d1;
#pragma unroll
        for (int off = 16; off; off >>= 1) {
            pa += __shfl_xor_sync(0xffffffffu, pa, off);
            pd += __shfl_xor_sync(0xffffffffu, pd, off);
        }
        if (lane == 0) {
            g_as2[row] = pa;
            g_ad2[row] = pd;
        }
    }
}

// ---------------- layer-2 gather aggregation fused with final projection ----------------
__global__ void k_agg2f(const float* __restrict__ b2, const float* __restrict__ Wc,
                        const float* __restrict__ bc, float* __restrict__ out) {
    int n = blockIdx.x * 8 + (threadIdx.x >> 5);
    if (n >= NN) return;
    int lane = threadIdx.x & 31;
    int grp = lane >> 3;
    int q = lane & 7;

    int rs = g_rs[n];
    int deg = g_cnt[n];
    float adv = g_ad2[n];

    float a0 = 0.f, a1 = 0.f, a2 = 0.f, a3 = 0.f;
    float a4 = 0.f, a5 = 0.f, a6 = 0.f, a7 = 0.f, den = 0.f;

    const float4* h4 = (const float4*)g_h2h;
    for (int j = 0; j < deg; j += 8) {
        int j0 = j + grp, j1 = j + grp + 4;
        int s0 = g_srcs[rs + (j0 < deg ? j0 : deg - 1)];
        int s1 = g_srcs[rs + (j1 < deg ? j1 : deg - 1)];
        float c0 = g_as2[s0];
        float c1 = g_as2[s1];
        float4 r0 = h4[s0 * 8 + q];
        float4 r1 = h4[s1 * 8 + q];
        float e0 = (j0 < deg) ? __expf(lrelu(c0 + adv)) : 0.f;
        float e1 = (j1 < deg) ? __expf(lrelu(c1 + adv)) : 0.f;
        den += e0 + e1;
        const __half2* p0 = (const __half2*)&r0;
        const __half2* p1 = (const __half2*)&r1;
        float2 v;
        v = __half22float2(p0[0]); a0 += e0 * v.x; a1 += e0 * v.y;
        v = __half22float2(p0[1]); a2 += e0 * v.x; a3 += e0 * v.y;
        v = __half22float2(p0[2]); a4 += e0 * v.x; a5 += e0 * v.y;
        v = __half22float2(p0[3]); a6 += e0 * v.x; a7 += e0 * v.y;
        v = __half22float2(p1[0]); a0 += e1 * v.x; a1 += e1 * v.y;
        v = __half22float2(p1[1]); a2 += e1 * v.x; a3 += e1 * v.y;
        v = __half22float2(p1[2]); a4 += e1 * v.x; a5 += e1 * v.y;
        v = __half22float2(p1[3]); a6 += e1 * v.x; a7 += e1 * v.y;
    }
    // den: all 8 lanes of a group hold the group's den; groups partition edges.
#pragma unroll
    for (int off = 8; off <= 16; off <<= 1) {
        den += __shfl_xor_sync(0xffffffffu, den, off);
        a0 += __shfl_xor_sync(0xffffffffu, a0, off);
        a1 += __shfl_xor_sync(0xffffffffu, a1, off);
        a2 += __shfl_xor_sync(0xffffffffu, a2, off);
        a3 += __shfl_xor_sync(0xffffffffu, a3, off);
        a4 += __shfl_xor_sync(0xffffffffu, a4, off);
        a5 += __shfl_xor_sync(0xffffffffu, a5, off);
        a6 += __shfl_xor_sync(0xffffffffu, a6, off);
        a7 += __shfl_xor_sync(0xffffffffu, a7, off);
    }
    float inv = 1.f / (den + 1e-16f);
    // projection over this lane's 8 features, then butterfly over q (xor 1,2,4)
    float4 ba = ((const float4*)b2)[q * 2],  bb = ((const float4*)b2)[q * 2 + 1];
    float4 wa = ((const float4*)Wc)[q * 2],  wb = ((const float4*)Wc)[q * 2 + 1];
    float v = fmaxf(a0 * inv + ba.x, 0.f) * wa.x
            + fmaxf(a1 * inv + ba.y, 0.f) * wa.y
            + fmaxf(a2 * inv + ba.z, 0.f) * wa.z
            + fmaxf(a3 * inv + ba.w, 0.f) * wa.w
            + fmaxf(a4 * inv + bb.x, 0.f) * wb.x
            + fmaxf(a5 * inv + bb.y, 0.f) * wb.y
            + fmaxf(a6 * inv + bb.z, 0.f) * wb.z
            + fmaxf(a7 * inv + bb.w, 0.f) * wb.w;
#pragma unroll
    for (int off = 1; off <= 4; off <<= 1) v += __shfl_xor_sync(0xffffffffu, v, off);
    if (lane == 0) {
        out[n] = v + __ldg(&bc[0]);
        g_cnt[n] = 0;  // restore invariant for next call's histogram
    }
}

extern "C" void kernel_launch(void* const* d_in, const int* in_sizes, int n_in,
                              void* d_out, int out_size) {
    const float* x      = (const float*)d_in[0];
    const int* ei       = (const int*)d_in[1];   // JAX x64 disabled -> int32
    const float* W1     = (const float*)d_in[2];
    const float* a_src1 = (const float*)d_in[3];
    const float* a_dst1 = (const float*)d_in[4];
    const float* b1     = (const float*)d_in[5];
    const float* W2     = (const float*)d_in[6];
    const float* a_src2 = (const float*)d_in[7];
    const float* a_dst2 = (const float*)d_in[8];
    const float* b2     = (const float*)d_in[9];
    const float* Wc     = (const float*)d_in[10];
    const float* bc     = (const float*)d_in[11];
    float* out          = (float*)d_out;
    (void)in_sizes; (void)n_in; (void)out_size;

    k_gemm1h<<<3125, 256>>>(x, W1, a_src1, a_dst1, ei);  // 1: GEMM1 + degree hist
    k_alloc<<<(NN + 255) / 256, 256>>>();                // 2: CSR range alloc
    k_fill<<<(EE + 255) / 256, 256>>>(ei);               // 3: CSR fill
    k_agg1<<<12500, 256>>>();                            // 4: <- ncu sample
    k_gemm2<<<3125, 256>>>(W2, b1, a_src2, a_dst2);      // 5
    k_agg2f<<<12500, 256>>>(b2, Wc, bc, out);            // 6
}